// round 2
// baseline (speedup 1.0000x reference)
#include <cuda_runtime.h>
#include <math.h>

#define DN   128
#define HK   65
#define BN   4
#define TN   2
#define GN   125
#define PERB (TN*GN)      // 250
#define NBTG (BN*PERB)    // 1000
#define WIN  24
#define H0   52

// ---------------- scratch (static device memory; no allocation) ----------------
__device__ float2 g_vf[DN*DN*HK];     // vol rfft, z/y fftshifted, x natural (8.5 MB)
__device__ float2 g_fimg[BN*DN*HK];   // image rffts, y fftshifted
__device__ float  g_corr[NBTG];
__device__ int    g_argm[NBTG];

__device__ __forceinline__ float2 cmulf(float2 a, float2 b){
    return make_float2(a.x*b.x - a.y*b.y, a.x*b.y + a.y*b.x);
}

// ---------------- in-place 128-pt forward FFT (radix-2 DIF + bitrev) ----------
// requires exactly 128 threads; Ef[j] = exp(-2*pi*i*j/128)
__device__ void fft128(float2* a, const float2* Ef, int tid){
    for (int size = 128; size >= 2; size >>= 1){
        int half = size >> 1;
        if (tid < 64){
            int grp  = tid / half;
            int j    = tid - grp*half;
            int base = grp*size + j;
            float2 u = a[base];
            float2 v = a[base+half];
            float2 d = make_float2(u.x - v.x, u.y - v.y);
            a[base]      = make_float2(u.x + v.x, u.y + v.y);
            a[base+half] = cmulf(d, Ef[j * (128/size)]);
        }
        __syncthreads();
    }
    float2 r = a[tid];
    int br = (int)(__brev((unsigned)tid) >> 25);
    __syncthreads();
    a[br] = r;
    __syncthreads();
}

__device__ __forceinline__ void make_fwd_table(float2* Ef, int tid){
    float s, c;
    sincosf(-6.283185307179586f * (float)tid * (1.0f/128.0f), &s, &c);
    Ef[tid] = make_float2(c, s);
}

// ---------------- volume forward rfft (3 passes) ----------------
// Pass X: weight by sinc(r)^2, x-fftshift at load, rfft along x.
__global__ void kVolX(const float* __restrict__ vol){
    __shared__ float2 a[128];
    __shared__ float2 Ef[128];
    int tid = threadIdx.x;
    int z = blockIdx.x >> 7;
    int y = blockIdx.x & 127;
    make_fwd_table(Ef, tid);

    float fz = (float)(z - 64) * (1.0f/128.0f);
    float fy = (float)(y - 64) * (1.0f/128.0f);
    float fx = (float)(tid - 64) * (1.0f/128.0f);
    float r  = sqrtf(fz*fz + fy*fy + fx*fx);
    float w;
    if (r < 1e-12f) w = 1.0f;
    else { float pr = 3.14159265358979f * r; w = sinf(pr) / pr; }
    w = w * w;
    float val = vol[(z*DN + y)*DN + tid] * w;
    a[(tid + 64) & 127] = make_float2(val, 0.0f);
    __syncthreads();
    fft128(a, Ef, tid);
    if (tid < HK) g_vf[(z*DN + y)*HK + tid] = a[tid];
}

// Pass Y: y-fftshift at load, C2C fft along y, ky-fftshift at store (in-place per column)
__global__ void kVolY(){
    __shared__ float2 a[128];
    __shared__ float2 Ef[128];
    int tid = threadIdx.x;
    int z  = blockIdx.x / HK;
    int kx = blockIdx.x % HK;
    make_fwd_table(Ef, tid);
    int ys = (tid + 64) & 127;
    a[tid] = g_vf[(z*DN + ys)*HK + kx];
    __syncthreads();
    fft128(a, Ef, tid);
    g_vf[(z*DN + ys)*HK + kx] = a[tid];
}

// Pass Z: z-fftshift at load, C2C fft along z, kz-fftshift at store
__global__ void kVolZ(){
    __shared__ float2 a[128];
    __shared__ float2 Ef[128];
    int tid = threadIdx.x;
    int sy = blockIdx.x / HK;
    int kx = blockIdx.x % HK;
    make_fwd_table(Ef, tid);
    int zs = (tid + 64) & 127;
    a[tid] = g_vf[(zs*DN + sy)*HK + kx];
    __syncthreads();
    fft128(a, Ef, tid);
    g_vf[(zs*DN + sy)*HK + kx] = a[tid];
}

// ---------------- image forward rfft (2 passes) ----------------
__global__ void kImgX(const float* __restrict__ imgs){
    __shared__ float2 a[128];
    __shared__ float2 Ef[128];
    int tid = threadIdx.x;
    int b = blockIdx.x >> 7;
    int y = blockIdx.x & 127;
    make_fwd_table(Ef, tid);
    float val = imgs[(b*DN + y)*DN + tid];
    a[(tid + 64) & 127] = make_float2(val, 0.0f);
    __syncthreads();
    fft128(a, Ef, tid);
    if (tid < HK) g_fimg[(b*DN + y)*HK + tid] = a[tid];
}

__global__ void kImgY(){
    __shared__ float2 a[128];
    __shared__ float2 Ef[128];
    int tid = threadIdx.x;
    int b  = blockIdx.x / HK;
    int kx = blockIdx.x % HK;
    make_fwd_table(Ef, tid);
    int ys = (tid + 64) & 127;
    a[tid] = g_fimg[(b*DN + ys)*HK + kx];
    __syncthreads();
    fft128(a, Ef, tid);
    g_fimg[(b*DN + ys)*HK + kx] = a[tid];
}

// ---------------- main matcher: one block per (b,t,g) ----------------
__global__ void __launch_bounds__(256) kMatch(const float* __restrict__ ctf,
                                              const float* __restrict__ rotm,
                                              const float* __restrict__ gridm){
    __shared__ float2 Pp[32][HK];     // product stripe (signs/alpha folded)
    __shared__ float2 G1[128][WIN];   // stage-1 result
    __shared__ float2 Ei[128];        // exp(+2*pi*i*j/128)
    __shared__ float  Ac[3], Bc[3];
    __shared__ float  rv[256];
    __shared__ int    ri[256];

    int tid = threadIdx.x;
    int bid = blockIdx.x;
    int b  = bid / PERB;
    int rr = bid % PERB;
    int t  = rr / GN;
    int g  = rr % GN;

    if (tid < 128){
        float s, c;
        sincosf(6.283185307179586f * (float)tid * (1.0f/128.0f), &s, &c);
        Ei[tid] = make_float2(c, s);
    }
    if (tid < 3){
        // exp_R[i][k] = sum_j rot[b,t,i,j] * grid[g,j,k];  Rzyx[i][j] = exp_R[2-i][2-j]
        // A_i = Rzyx[i][1] = exp_R[2-i][1] ; B_i = Rzyx[i][2] = exp_R[2-i][0]
        int i  = tid;
        int ii = 2 - i;
        const float* R  = rotm  + ((b*TN + t)*3 + ii)*3;
        const float* Gm = gridm + g*9;
        Ac[i] = R[0]*Gm[1] + R[1]*Gm[4] + R[2]*Gm[7];
        Bc[i] = R[0]*Gm[0] + R[1]*Gm[3] + R[2]*Gm[6];
    }
    __syncthreads();
    float A0=Ac[0], A1=Ac[1], A2=Ac[2], B0=Bc[0], B1=Bc[1], B2=Bc[2];

    const float*  ctfb = ctf    + b*DN*HK;
    const float2* fib  = g_fimg + b*DN*HK;

    for (int stripe = 0; stripe < 4; stripe++){
        int hbase = stripe * 32;
        // ---- stage 0: slice extraction + product ----
        for (int idx = tid; idx < 32*HK; idx += 256){
            int hh = idx / HK;
            int l  = idx - hh*HK;
            int h  = hbase + hh;
            float hm = (float)(h - 64);
            float lf = (float)l;
            float v0 = A0*hm + B0*lf;
            float v1 = A1*hm + B1*lf;
            float v2 = A2*hm + B2*lf;
            bool neg = (v2 < 0.0f);
            if (neg){ v0 = -v0; v1 = -v1; v2 = -v2; }
            float zc = v0 + 64.0f, yc = v1 + 64.0f, xc = v2;
            float zf = floorf(zc), yf = floorf(yc), xf = floorf(xc);
            int z0 = (int)zf, y0 = (int)yf, x0 = (int)xf;
            float fz = zc - zf, fy = yc - yf, fx = xc - xf;
            float2 acc = make_float2(0.0f, 0.0f);
            #pragma unroll
            for (int dz = 0; dz < 2; dz++){
                int zi = z0 + dz;
                if (zi < 0 || zi >= DN) continue;
                float wz = dz ? fz : 1.0f - fz;
                #pragma unroll
                for (int dy = 0; dy < 2; dy++){
                    int yi = y0 + dy;
                    if (yi < 0 || yi >= DN) continue;
                    float wzy = wz * (dy ? fy : 1.0f - fy);
                    #pragma unroll
                    for (int dx = 0; dx < 2; dx++){
                        int xi = x0 + dx;
                        if (xi < 0 || xi >= HK) continue;
                        float ww = wzy * (dx ? fx : 1.0f - fx);
                        float2 vv = __ldg(&g_vf[(zi*DN + yi)*HK + xi]);
                        acc.x += vv.x * ww;
                        acc.y += vv.y * ww;
                    }
                }
            }
            if (neg) acc.y = -acc.y;                 // conj
            float  cf = __ldg(&ctfb[h*HK + l]);
            float2 fi = fib[h*HK + l];
            // prod = fimg * conj(proj), proj = sample * ctf  (ctf real)
            float px = cf * (fi.x*acc.x + fi.y*acc.y);
            float py = cf * (fi.y*acc.x - fi.x*acc.y);
            float sgn = ((h + l) & 1) ? -1.0f : 1.0f;
            if (l != 0 && l != 64) sgn *= 2.0f;      // Hermitian alpha weight
            Pp[hh][l] = make_float2(px*sgn, py*sgn);
        }
        __syncthreads();
        // ---- stage 1: contract x-frequencies (65) -> 24 output columns ----
        for (int task = tid; task < 32*WIN; task += 256){
            int hh = task / WIN;
            int v  = task - hh*WIN;
            float2 step = Ei[H0 + v];
            float2 w    = make_float2(1.0f, 0.0f);
            float2 acc  = make_float2(0.0f, 0.0f);
            for (int l = 0; l < HK; l++){
                float2 p = Pp[hh][l];
                acc.x += p.x*w.x - p.y*w.y;
                acc.y += p.x*w.y + p.y*w.x;
                float wx = w.x*step.x - w.y*step.y;
                w.y = w.x*step.y + w.y*step.x;
                w.x = wx;
            }
            G1[hbase + hh][v] = acc;
        }
        __syncthreads();
    }
    // ---- stage 2: contract rows (128) -> 24 output rows, take Re ----
    float best = -3.4e38f;
    int bestIdx = 0x7fffffff;
    for (int task = tid; task < WIN*WIN; task += 256){
        int u = task / WIN;
        int v = task - u*WIN;
        float2 step = Ei[H0 + u];
        float2 w    = make_float2(1.0f, 0.0f);
        float acc = 0.0f;
        for (int h = 0; h < 128; h++){
            float2 gv = G1[h][v];
            acc += gv.x*w.x - gv.y*w.y;
            float wx = w.x*step.x - w.y*step.y;
            w.y = w.x*step.y + w.y*step.x;
            w.x = wx;
        }
        float val = acc * (1.0f/16384.0f);
        if (u & 1) val = -val;                       // (-1)^(52+u)
        if (val > best || (val == best && task < bestIdx)){ best = val; bestIdx = task; }
    }
    rv[tid] = best; ri[tid] = bestIdx;
    __syncthreads();
    for (int s = 128; s; s >>= 1){
        if (tid < s){
            float v2 = rv[tid+s]; int i2 = ri[tid+s];
            if (v2 > rv[tid] || (v2 == rv[tid] && i2 < ri[tid])){ rv[tid] = v2; ri[tid] = i2; }
        }
        __syncthreads();
    }
    if (tid == 0){ g_corr[bid] = rv[0]; g_argm[bid] = ri[0]; }
}

// ---------------- final per-batch reduction ----------------
__global__ void __launch_bounds__(256) kReduce(const float* __restrict__ gridm,
                                               float* __restrict__ out){
    __shared__ float sv[256];
    __shared__ int   si[256];
    __shared__ float s_mean, s_std;
    __shared__ float s_val[2];
    __shared__ int   s_idx[2];
    int b = blockIdx.x, tid = threadIdx.x;
    float v = (tid < PERB) ? g_corr[b*PERB + tid] : 0.0f;

    sv[tid] = (tid < PERB) ? v : 0.0f;
    __syncthreads();
    for (int s = 128; s; s >>= 1){ if (tid < s) sv[tid] += sv[tid+s]; __syncthreads(); }
    if (tid == 0) s_mean = sv[0] / (float)PERB;
    __syncthreads();
    float mean = s_mean;
    float d = (tid < PERB) ? (v - mean) : 0.0f;
    sv[tid] = d * d;
    __syncthreads();
    for (int s = 128; s; s >>= 1){ if (tid < s) sv[tid] += sv[tid+s]; __syncthreads(); }
    if (tid == 0) s_std = sqrtf(sv[0] / (float)(PERB - 1));
    __syncthreads();
    float stdv = s_std;

    for (int k = 0; k < 2; k++){
        bool excl = (k == 1 && tid == s_idx[0]);
        sv[tid] = (tid < PERB && !excl) ? v : -3.4e38f;
        si[tid] = tid;
        __syncthreads();
        for (int s = 128; s; s >>= 1){
            if (tid < s){
                float v2 = sv[tid+s]; int i2 = si[tid+s];
                if (v2 > sv[tid] || (v2 == sv[tid] && i2 < si[tid])){ sv[tid] = v2; si[tid] = i2; }
            }
            __syncthreads();
        }
        if (tid == 0){ s_val[k] = sv[0]; s_idx[k] = si[0]; }
        __syncthreads();
    }

    if (tid < 2){
        int k = tid;
        float val = s_val[k];
        int   idx = s_idx[k];
        int   gg  = idx % GN;
        int   a   = g_argm[b*PERB + idx];
        int   u   = a / WIN;
        int   vv  = a - u*WIN;
        int slot  = b*2 + k;
        // layout: maxCorrs[8] | predRotMats[72] | predShiftsAngs[16] | comparedWeight[8]
        out[slot] = val;
        for (int j = 0; j < 9; j++) out[8 + slot*9 + j] = gridm[gg*9 + j];
        out[80 + slot*2 + 0] = -((float)(H0 + vv) - 64.0f) * 1.5f;
        out[80 + slot*2 + 1] = -((float)(H0 + u)  - 64.0f) * 1.5f;
        float zz = (val - mean) / (stdv * 1.41421356237f);
        out[96 + slot] = 0.5f * (1.0f + erff(zz));
    }
}

// ---------------- launch ----------------
extern "C" void kernel_launch(void* const* d_in, const int* in_sizes, int n_in,
                              void* d_out, int out_size){
    const float* vol   = (const float*)d_in[0];
    const float* imgs  = (const float*)d_in[1];
    const float* ctf   = (const float*)d_in[2];
    const float* rotm  = (const float*)d_in[3];
    const float* gridm = (const float*)d_in[4];

    kVolX<<<DN*DN, 128>>>(vol);
    kVolY<<<DN*HK, 128>>>();
    kVolZ<<<DN*HK, 128>>>();
    kImgX<<<BN*DN, 128>>>(imgs);
    kImgY<<<BN*HK, 128>>>();
    kMatch<<<NBTG, 256>>>(ctf, rotm, gridm);
    kReduce<<<BN, 256>>>(gridm, (float*)d_out);
}

// round 4
// speedup vs baseline: 1.1095x; 1.1095x over previous
#include <cuda_runtime.h>
#include <math.h>

#define DN   128
#define HK   65
#define BN   4
#define TN   2
#define GN   125
#define PERB (TN*GN)      // 250
#define NBTG (BN*PERB)    // 1000
#define WIN  24
#define H0   52
#define KT   9            // ceil(65/8) kx tiles

// ---------------- scratch (static device memory; no allocation) ----------------
__device__ float2 g_vf[DN*DN*HK];     // vol rfft, z/y fftshifted, x natural (8.5 MB)
__device__ float2 g_fimg[BN*DN*HK];   // image rffts, y fftshifted
__device__ float2 g_tw[128];          // exp(-2*pi*i*j/128)
__device__ float  g_corr[NBTG];
__device__ int    g_argm[NBTG];

__device__ __forceinline__ float2 cmulf(float2 a, float2 b){
    return make_float2(a.x*b.x - a.y*b.y, a.x*b.y + a.y*b.x);
}

// ---------------- one-time twiddle table ----------------
__global__ void kInit(){
    int j = threadIdx.x;
    float s, c;
    sincosf(-6.283185307179586f * (float)j * (1.0f/128.0f), &s, &c);
    g_tw[j] = make_float2(c, s);
}

// ---------------- in-place 128-pt forward FFT, 128 threads (radix-2 DIF) -----
__device__ void fft128(float2* a, const float2* Ef, int tid){
    for (int size = 128; size >= 2; size >>= 1){
        int half = size >> 1;
        if (tid < 64){
            int grp  = tid / half;
            int j    = tid - grp*half;
            int base = grp*size + j;
            float2 u = a[base];
            float2 v = a[base+half];
            float2 d = make_float2(u.x - v.x, u.y - v.y);
            a[base]      = make_float2(u.x + v.x, u.y + v.y);
            a[base+half] = cmulf(d, Ef[j * (128/size)]);
        }
        __syncthreads();
    }
    float2 r = a[tid];
    int br = (int)(__brev((unsigned)tid) >> 25);
    __syncthreads();
    a[br] = r;
    __syncthreads();
}

// ---------------- warp-local 128-pt FFT: one warp, 2 butterflies/thread ------
__device__ __forceinline__ void fft128_w32(float2* col, const float2* Ef, int lane){
    for (int shift = 6; shift >= 0; shift--){
        int half = 1 << shift;
        int twsh = 6 - shift;               // Ef stride = 1 << twsh
        #pragma unroll
        for (int k = 0; k < 2; k++){
            int bf   = lane + k*32;         // 0..63
            int j    = bf & (half - 1);
            int grp  = bf >> shift;
            int base = (grp << (shift + 1)) + j;
            float2 u = col[base];
            float2 v = col[base + half];
            float2 d = make_float2(u.x - v.x, u.y - v.y);
            col[base]        = make_float2(u.x + v.x, u.y + v.y);
            col[base + half] = cmulf(d, Ef[j << twsh]);
        }
        __syncwarp();
    }
    float2 r[4];
    #pragma unroll
    for (int k = 0; k < 4; k++) r[k] = col[lane + k*32];
    __syncwarp();
    #pragma unroll
    for (int k = 0; k < 4; k++){
        int y = lane + k*32;
        col[(int)(__brev((unsigned)y) >> 25)] = r[k];
    }
    __syncwarp();
}

// ---------------- volume forward rfft (3 passes) ----------------
// Pass X: weight by sinc(r)^2, x-fftshift at load, rfft along x.
__global__ void kVolX(const float* __restrict__ vol){
    __shared__ float2 a[128];
    __shared__ float2 Ef[128];
    int tid = threadIdx.x;
    int z = blockIdx.x >> 7;
    int y = blockIdx.x & 127;
    Ef[tid] = g_tw[tid];

    float fz = (float)(z - 64) * (1.0f/128.0f);
    float fy = (float)(y - 64) * (1.0f/128.0f);
    float fx = (float)(tid - 64) * (1.0f/128.0f);
    float r  = sqrtf(fz*fz + fy*fy + fx*fx);
    float w;
    if (r < 1e-12f) w = 1.0f;
    else { float pr = 3.14159265358979f * r; w = __sinf(pr) / pr; }
    w = w * w;
    float val = vol[(z*DN + y)*DN + tid] * w;
    a[(tid + 64) & 127] = make_float2(val, 0.0f);
    __syncthreads();
    fft128(a, Ef, tid);
    if (tid < HK) g_vf[(z*DN + y)*HK + tid] = a[tid];
}

// Pass Y (tiled): block = (z, 8-wide kx tile); coalesced 64B segments,
// warp-local FFT per column, y-fftshift folded into both load and store.
__global__ void __launch_bounds__(256) kVolYT(){
    __shared__ float2 a[8][128];
    __shared__ float2 Ef[128];
    int tid = threadIdx.x;
    int z   = blockIdx.x / KT;
    int kt  = blockIdx.x % KT;
    int kx0 = kt * 8;
    if (tid < 128) Ef[tid] = g_tw[tid];
    #pragma unroll
    for (int k = 0; k < 4; k++){
        int idx = tid + k*256;
        int y = idx >> 3, c = idx & 7;
        int kx = kx0 + c;
        if (kx < HK){
            int ys = (y + 64) & 127;
            a[c][y] = g_vf[(z*DN + ys)*HK + kx];
        }
    }
    __syncthreads();
    int wid = tid >> 5, lane = tid & 31;
    if (kx0 + wid < HK) fft128_w32(a[wid], Ef, lane);
    __syncthreads();
    #pragma unroll
    for (int k = 0; k < 4; k++){
        int idx = tid + k*256;
        int y = idx >> 3, c = idx & 7;
        int kx = kx0 + c;
        if (kx < HK){
            int ys = (y + 64) & 127;
            g_vf[(z*DN + ys)*HK + kx] = a[c][y];
        }
    }
}

// Pass Z (tiled): block = (sy, 8-wide kx tile); FFT along z.
__global__ void __launch_bounds__(256) kVolZT(){
    __shared__ float2 a[8][128];
    __shared__ float2 Ef[128];
    int tid = threadIdx.x;
    int sy  = blockIdx.x / KT;
    int kt  = blockIdx.x % KT;
    int kx0 = kt * 8;
    if (tid < 128) Ef[tid] = g_tw[tid];
    #pragma unroll
    for (int k = 0; k < 4; k++){
        int idx = tid + k*256;
        int zz = idx >> 3, c = idx & 7;
        int kx = kx0 + c;
        if (kx < HK){
            int zs = (zz + 64) & 127;
            a[c][zz] = g_vf[(zs*DN + sy)*HK + kx];
        }
    }
    __syncthreads();
    int wid = tid >> 5, lane = tid & 31;
    if (kx0 + wid < HK) fft128_w32(a[wid], Ef, lane);
    __syncthreads();
    #pragma unroll
    for (int k = 0; k < 4; k++){
        int idx = tid + k*256;
        int zz = idx >> 3, c = idx & 7;
        int kx = kx0 + c;
        if (kx < HK){
            int zs = (zz + 64) & 127;
            g_vf[(zs*DN + sy)*HK + kx] = a[c][zz];
        }
    }
}

// ---------------- image forward rfft (2 passes) ----------------
__global__ void kImgX(const float* __restrict__ imgs){
    __shared__ float2 a[128];
    __shared__ float2 Ef[128];
    int tid = threadIdx.x;
    int b = blockIdx.x >> 7;
    int y = blockIdx.x & 127;
    Ef[tid] = g_tw[tid];
    float val = imgs[(b*DN + y)*DN + tid];
    a[(tid + 64) & 127] = make_float2(val, 0.0f);
    __syncthreads();
    fft128(a, Ef, tid);
    if (tid < HK) g_fimg[(b*DN + y)*HK + tid] = a[tid];
}

__global__ void kImgY(){
    __shared__ float2 a[128];
    __shared__ float2 Ef[128];
    int tid = threadIdx.x;
    int b  = blockIdx.x / HK;
    int kx = blockIdx.x % HK;
    Ef[tid] = g_tw[tid];
    int ys = (tid + 64) & 127;
    a[tid] = g_fimg[(b*DN + ys)*HK + kx];
    __syncthreads();
    fft128(a, Ef, tid);
    g_fimg[(b*DN + ys)*HK + kx] = a[tid];
}

// ---------------- main matcher: one block per (b,t,g) ----------------
__global__ void __launch_bounds__(256) kMatch(const float* __restrict__ ctf,
                                              const float* __restrict__ rotm,
                                              const float* __restrict__ gridm){
    __shared__ float2 Pp[32][HK];     // product stripe (signs/alpha folded)
    __shared__ float2 G1[128][WIN];   // stage-1 result
    __shared__ float2 Ei[128];        // exp(+2*pi*i*j/128)
    __shared__ float  Ac[3], Bc[3];
    __shared__ float  rv[256];
    __shared__ int    ri[256];

    int tid = threadIdx.x;
    int bid = blockIdx.x;
    int b  = bid / PERB;
    int rr = bid % PERB;
    int t  = rr / GN;
    int g  = rr % GN;

    if (tid < 128){
        float2 tw = g_tw[tid];
        Ei[tid] = make_float2(tw.x, -tw.y);   // conj -> exp(+i...)
    }
    if (tid < 3){
        // exp_R[i][k] = sum_j rot[b,t,i,j] * grid[g,j,k];  Rzyx[i][j] = exp_R[2-i][2-j]
        // A_i = Rzyx[i][1] = exp_R[2-i][1] ; B_i = Rzyx[i][2] = exp_R[2-i][0]
        int i  = tid;
        int ii = 2 - i;
        const float* R  = rotm  + ((b*TN + t)*3 + ii)*3;
        const float* Gm = gridm + g*9;
        Ac[i] = R[0]*Gm[1] + R[1]*Gm[4] + R[2]*Gm[7];
        Bc[i] = R[0]*Gm[0] + R[1]*Gm[3] + R[2]*Gm[6];
    }
    __syncthreads();
    float A0=Ac[0], A1=Ac[1], A2=Ac[2], B0=Bc[0], B1=Bc[1], B2=Bc[2];

    const float*  ctfb = ctf    + b*DN*HK;
    const float2* fib  = g_fimg + b*DN*HK;

    int hh1  = tid & 31;        // stage-1 row for this thread
    int grp1 = tid >> 5;        // stage-1 column group (0..7), covers v = 3*grp1 + {0,1,2}
    int sb0  = H0 + 3*grp1;     // twiddle steps sb0, sb0+1, sb0+2

    for (int stripe = 0; stripe < 4; stripe++){
        int hbase = stripe * 32;
        // ---- stage 0: slice extraction + product ----
        for (int idx = tid; idx < 32*HK; idx += 256){
            int hh = idx / HK;
            int l  = idx - hh*HK;
            int h  = hbase + hh;
            float hm = (float)(h - 64);
            float lf = (float)l;
            float v0 = A0*hm + B0*lf;
            float v1 = A1*hm + B1*lf;
            float v2 = A2*hm + B2*lf;
            bool neg = (v2 < 0.0f);
            if (neg){ v0 = -v0; v1 = -v1; v2 = -v2; }
            float zc = v0 + 64.0f, yc = v1 + 64.0f, xc = v2;
            float zf = floorf(zc), yf = floorf(yc), xf = floorf(xc);
            int z0 = (int)zf, y0 = (int)yf, x0 = (int)xf;
            float fz = zc - zf, fy = yc - yf, fx = xc - xf;
            float2 acc = make_float2(0.0f, 0.0f);
            #pragma unroll
            for (int dz = 0; dz < 2; dz++){
                int zi = z0 + dz;
                if (zi < 0 || zi >= DN) continue;
                float wz = dz ? fz : 1.0f - fz;
                #pragma unroll
                for (int dy = 0; dy < 2; dy++){
                    int yi = y0 + dy;
                    if (yi < 0 || yi >= DN) continue;
                    float wzy = wz * (dy ? fy : 1.0f - fy);
                    #pragma unroll
                    for (int dx = 0; dx < 2; dx++){
                        int xi = x0 + dx;
                        if (xi < 0 || xi >= HK) continue;
                        float ww = wzy * (dx ? fx : 1.0f - fx);
                        float2 vv = __ldg(&g_vf[(zi*DN + yi)*HK + xi]);
                        acc.x += vv.x * ww;
                        acc.y += vv.y * ww;
                    }
                }
            }
            if (neg) acc.y = -acc.y;                 // conj
            float  cf = __ldg(&ctfb[h*HK + l]);
            float2 fi = fib[h*HK + l];
            // prod = fimg * conj(proj), proj = sample * ctf  (ctf real)
            float px = cf * (fi.x*acc.x + fi.y*acc.y);
            float py = cf * (fi.y*acc.x - fi.x*acc.y);
            float sgn = ((h + l) & 1) ? -1.0f : 1.0f;
            if (l != 0 && l != 64) sgn *= 2.0f;      // Hermitian alpha weight
            Pp[hh][l] = make_float2(px*sgn, py*sgn);
        }
        __syncthreads();
        // ---- stage 1: contract 65 x-freqs -> 24 output columns.
        // Thread handles row hh1, columns v = 3*grp1 + {0,1,2}; twiddles via
        // integer-indexed roots (no serial recurrence), p reused 3x.
        {
            float2 a0 = make_float2(0.f,0.f), a1 = a0, a2 = a0;
            int i0 = 0, i1 = 0, i2 = 0;
            for (int l = 0; l < HK; l++){
                float2 p  = Pp[hh1][l];
                float2 w0 = Ei[i0];
                float2 w1 = Ei[i1];
                float2 w2 = Ei[i2];
                a0.x += p.x*w0.x - p.y*w0.y;  a0.y += p.x*w0.y + p.y*w0.x;
                a1.x += p.x*w1.x - p.y*w1.y;  a1.y += p.x*w1.y + p.y*w1.x;
                a2.x += p.x*w2.x - p.y*w2.y;  a2.y += p.x*w2.y + p.y*w2.x;
                i0 = (i0 + sb0    ) & 127;
                i1 = (i1 + sb0 + 1) & 127;
                i2 = (i2 + sb0 + 2) & 127;
            }
            int row = hbase + hh1, vb = 3*grp1;
            G1[row][vb+0] = a0;
            G1[row][vb+1] = a1;
            G1[row][vb+2] = a2;
        }
        __syncthreads();
    }
    // ---- stage 2: contract 128 rows -> 24 output rows, take Re ----
    float best = -3.4e38f;
    int bestIdx = 0x7fffffff;
    if (tid < 192){
        int v  = tid % 24;
        int ug = tid / 24;          // 0..7 -> u = 3*ug + {0,1,2}
        int ub0 = H0 + 3*ug;
        float r0 = 0.f, r1 = 0.f, r2 = 0.f;
        int i0 = 0, i1 = 0, i2 = 0;
        for (int h = 0; h < 128; h++){
            float2 gv = G1[h][v];
            float2 w0 = Ei[i0];
            float2 w1 = Ei[i1];
            float2 w2 = Ei[i2];
            r0 += gv.x*w0.x - gv.y*w0.y;
            r1 += gv.x*w1.x - gv.y*w1.y;
            r2 += gv.x*w2.x - gv.y*w2.y;
            i0 = (i0 + ub0    ) & 127;
            i1 = (i1 + ub0 + 1) & 127;
            i2 = (i2 + ub0 + 2) & 127;
        }
        #pragma unroll
        for (int j = 0; j < 3; j++){
            int u = 3*ug + j;
            float val = (j == 0 ? r0 : (j == 1 ? r1 : r2)) * (1.0f/16384.0f);
            if (u & 1) val = -val;                  // (-1)^(52+u)
            int idx = u*WIN + v;
            if (val > best || (val == best && idx < bestIdx)){ best = val; bestIdx = idx; }
        }
    }
    rv[tid] = best; ri[tid] = bestIdx;
    __syncthreads();
    for (int s = 128; s; s >>= 1){
        if (tid < s){
            float v2 = rv[tid+s]; int i2 = ri[tid+s];
            if (v2 > rv[tid] || (v2 == rv[tid] && i2 < ri[tid])){ rv[tid] = v2; ri[tid] = i2; }
        }
        __syncthreads();
    }
    if (tid == 0){ g_corr[bid] = rv[0]; g_argm[bid] = ri[0]; }
}

// ---------------- final per-batch reduction ----------------
__global__ void __launch_bounds__(256) kReduce(const float* __restrict__ gridm,
                                               float* __restrict__ out){
    __shared__ float sv[256];
    __shared__ int   si[256];
    __shared__ float s_mean, s_std;
    __shared__ float s_val[2];
    __shared__ int   s_idx[2];
    int b = blockIdx.x, tid = threadIdx.x;
    float v = (tid < PERB) ? g_corr[b*PERB + tid] : 0.0f;

    sv[tid] = (tid < PERB) ? v : 0.0f;
    __syncthreads();
    for (int s = 128; s; s >>= 1){ if (tid < s) sv[tid] += sv[tid+s]; __syncthreads(); }
    if (tid == 0) s_mean = sv[0] / (float)PERB;
    __syncthreads();
    float mean = s_mean;
    float d = (tid < PERB) ? (v - mean) : 0.0f;
    sv[tid] = d * d;
    __syncthreads();
    for (int s = 128; s; s >>= 1){ if (tid < s) sv[tid] += sv[tid+s]; __syncthreads(); }
    if (tid == 0) s_std = sqrtf(sv[0] / (float)(PERB - 1));
    __syncthreads();
    float stdv = s_std;

    for (int k = 0; k < 2; k++){
        bool excl = (k == 1 && tid == s_idx[0]);
        sv[tid] = (tid < PERB && !excl) ? v : -3.4e38f;
        si[tid] = tid;
        __syncthreads();
        for (int s = 128; s; s >>= 1){
            if (tid < s){
                float v2 = sv[tid+s]; int i2 = si[tid+s];
                if (v2 > sv[tid] || (v2 == sv[tid] && i2 < si[tid])){ sv[tid] = v2; si[tid] = i2; }
            }
            __syncthreads();
        }
        if (tid == 0){ s_val[k] = sv[0]; s_idx[k] = si[0]; }
        __syncthreads();
    }

    if (tid < 2){
        int k = tid;
        float val = s_val[k];
        int   idx = s_idx[k];
        int   gg  = idx % GN;
        int   a   = g_argm[b*PERB + idx];
        int   u   = a / WIN;
        int   vv  = a - u*WIN;
        int slot  = b*2 + k;
        // layout: maxCorrs[8] | predRotMats[72] | predShiftsAngs[16] | comparedWeight[8]
        out[slot] = val;
        for (int j = 0; j < 9; j++) out[8 + slot*9 + j] = gridm[gg*9 + j];
        out[80 + slot*2 + 0] = -((float)(H0 + vv) - 64.0f) * 1.5f;
        out[80 + slot*2 + 1] = -((float)(H0 + u)  - 64.0f) * 1.5f;
        float zz = (val - mean) / (stdv * 1.41421356237f);
        out[96 + slot] = 0.5f * (1.0f + erff(zz));
    }
}

// ---------------- launch ----------------
extern "C" void kernel_launch(void* const* d_in, const int* in_sizes, int n_in,
                              void* d_out, int out_size){
    const float* vol   = (const float*)d_in[0];
    const float* imgs  = (const float*)d_in[1];
    const float* ctf   = (const float*)d_in[2];
    const float* rotm  = (const float*)d_in[3];
    const float* gridm = (const float*)d_in[4];

    kInit<<<1, 128>>>();
    kVolX<<<DN*DN, 128>>>(vol);
    kVolYT<<<DN*KT, 256>>>();
    kVolZT<<<DN*KT, 256>>>();
    kImgX<<<BN*DN, 128>>>(imgs);
    kImgY<<<BN*HK, 128>>>();
    kMatch<<<NBTG, 256>>>(ctf, rotm, gridm);
    kReduce<<<BN, 256>>>(gridm, (float*)d_out);
}